// round 9
// baseline (speedup 1.0000x reference)
#include <cuda_runtime.h>
#include <cstdint>

#define DP    512
#define D     500
#define MDIM  250
#define NDIM  250
#define BATCH 1024
#define HDIM  512
#define ITERS 1000
#define RPC   16      // rows per cluster (8 per-CTA work-equivalent)
#define COLH  256     // columns owned per CTA (half of DP)
#define SROW  18      // ull stride per state column (16 rows + 2 pad; even -> 16B aligned)

typedef unsigned long long ull;

// ---------------- device scratch ----------------
__device__ float g_P [DP*DP];
__device__ float g_h1[BATCH*HDIM];
__device__ float g_h2[BATCH*HDIM];
__device__ float g_y [BATCH*DP];
__device__ float g_q [BATCH*DP];

// ---------------- helpers ----------------
__device__ __forceinline__ void ffma2(ull &d, ull a, ull b) {
    asm("fma.rn.f32x2 %0, %1, %2, %0;" : "+l"(d) : "l"(a), "l"(b));
}
__device__ __forceinline__ float2 unpk(ull a) {
    float2 f; asm("mov.b64 {%0,%1}, %2;" : "=f"(f.x), "=f"(f.y) : "l"(a)); return f;
}
__device__ __forceinline__ ull dup2(float v) {
    ull d; asm("mov.b64 %0, {%1,%1};" : "=l"(d) : "f"(v)); return d;
}
__device__ __forceinline__ uint32_t smem_u32(const void* p) {
    uint32_t a; asm("{ .reg .u64 t; cvta.to.shared.u64 t, %1; cvt.u32.u64 %0, t; }" : "=r"(a) : "l"(p)); return a;
}
__device__ __forceinline__ uint32_t mapa32(uint32_t laddr, uint32_t rank) {
    uint32_t r; asm("mapa.shared::cluster.u32 %0, %1, %2;" : "=r"(r) : "r"(laddr), "r"(rank)); return r;
}
__device__ __forceinline__ void st_cluster_u64(uint32_t addr, ull v) {
    asm volatile("st.shared::cluster.u64 [%0], %1;" :: "r"(addr), "l"(v) : "memory");
}
__device__ __forceinline__ uint32_t ctarank() {
    uint32_t r; asm("mov.u32 %0, %%cluster_ctarank;" : "=r"(r)); return r;
}
#define CLUSTER_SYNC() do { \
    asm volatile("barrier.cluster.arrive.aligned;" ::: "memory"); \
    asm volatile("barrier.cluster.wait.aligned;"   ::: "memory"); } while(0)

// ---------------- P = I - (Aaug_inv @ Aaug)^T ----------------
__global__ void computeP(const float* __restrict__ Aaug, const float* __restrict__ Ainv) {
    int idx = blockIdx.x * 256 + threadIdx.x;
    int i = idx & (DP - 1);
    int j = idx >> 9;
    float acc = 0.f;
    if (i < D && j < D) {
        acc = (i == j) ? 1.f : 0.f;
        for (int k = 0; k < MDIM; ++k)
            acc -= Aaug[k * D + i] * Ainv[j * MDIM + k];
    }
    g_P[i * DP + j] = acc;
}

// ---------------- front-end MLP GEMM ----------------
#define FLAG_RELU   1
#define FLAG_TRANSB 2
#define FLAG_CONCAT 4
__global__ void gemm16(const float* __restrict__ A, const float* __restrict__ A2,
                       const float* __restrict__ B, const float* __restrict__ bias,
                       float* __restrict__ C, int K, int Nr, int ldc, int flags) {
    __shared__ float As[16][16];
    __shared__ float Bs[16][17];
    int tx = threadIdx.x, ty = threadIdx.y;
    int m = blockIdx.y * 16 + ty;
    int n = blockIdx.x * 16 + tx;
    float acc = 0.f;
    for (int k0 = 0; k0 < K; k0 += 16) {
        int ka = k0 + tx;
        float av = 0.f;
        if (ka < K) {
            if (flags & FLAG_CONCAT) av = (ka < MDIM) ? A[m * MDIM + ka] : A2[m * MDIM + ka - MDIM];
            else                     av = A[m * K + ka];
        }
        As[ty][tx] = av;
        int kb = k0 + ty;
        float bv = 0.f;
        if (kb < K && n < Nr) bv = (flags & FLAG_TRANSB) ? B[n * K + kb] : B[kb * Nr + n];
        Bs[ty][tx] = bv;
        __syncthreads();
#pragma unroll
        for (int kk = 0; kk < 16; ++kk) acc += As[ty][kk] * Bs[kk][tx];
        __syncthreads();
    }
    if (n < ldc) {
        float v = 0.f;
        if (n < Nr) {
            v = acc + (bias ? bias[n] : 0.f);
            if (flags & FLAG_RELU) v = fmaxf(v, 0.f);
        }
        C[m * ldc + n] = v;
    }
}

// ---------------- persistent iteration kernel (2-CTA cluster, column-split) ----
// 64 clusters x 2 CTAs x 256 threads. Cluster owns 16 batch rows; CTA rank q owns
// P/output columns [q*256, q*256+256). Each CTA reads 512 KB of P per iteration.
// GEMM: warp w -> (cs = w&1 : 128-col sub-half, kq = w>>1 : 128-k quarter).
//   Lane owns 4 consecutive cols (one LDG.128/k). acc[16 rows][2 f32x2 pairs].
// Epilogue: warp w -> rows 2w,2w+1; lane covers local col jl = s*32+lane, s=0..7.
// Cross-CTA: per-row {norm partial, tval} via DSMEM xbuf; updated s columns pushed
// to peer sdup via st.shared::cluster. Two cluster barriers per iteration.
#define RED_OFF   (DP * SROW * 8)                   // 73728
#define Y_OFF     (RED_OFF + 8 * RPC * 128 * 4)     // +65536 -> 139264
#define Q_OFF     (Y_OFF + RPC * COLH * 4)          // +16384 -> 155648
#define XBUF_OFF  (Q_OFF + RPC * COLH * 4)          // +16384 -> 172032
#define SMEM_BYTES (XBUF_OFF + RPC * 8)             // 172160

__global__ void __launch_bounds__(256, 1) __cluster_dims__(2, 1, 1)
iterate_kernel(float* __restrict__ out) {
    extern __shared__ char smem[];
    ull*    sdup = (ull*)smem;                      // [512][SROW] dup {s,s}
    float*  redf = (float*)(smem + RED_OFF);        // [8][16][128]
    float*  yv   = (float*)(smem + Y_OFF);          // [16][256] local col slice
    float*  qv   = (float*)(smem + Q_OFF);          // [16][256]
    float2* xbuf = (float2*)(smem + XBUF_OFF);      // [16] peer {norm_part, tval}

    const int tid  = threadIdx.x;
    const int warp = tid >> 5, lane = tid & 31;
    const int cs = warp & 1, kq = warp >> 1;
    const uint32_t q = ctarank();
    const int rowbase = (blockIdx.x >> 1) * RPC;

    const uint32_t sdup_b = smem_u32(smem);
    const uint32_t peer_sdup = mapa32(sdup_b, 1 - q);
    const uint32_t peer_xbuf = mapa32(sdup_b + XBUF_OFF, 1 - q);

    { // stage local y/q slices; zero s
        for (int i = tid; i < RPC * COLH / 4; i += 256) {
            int r = i >> 6, j4 = i & 63;
            ((float4*)yv)[i] = *(const float4*)(g_y + (rowbase + r) * DP + q * COLH + j4 * 4);
            ((float4*)qv)[i] = *(const float4*)(g_q + (rowbase + r) * DP + q * COLH + j4 * 4);
        }
        for (int i = tid; i < DP * SROW; i += 256) sdup[i] = 0ull;
    }
    CLUSTER_SYNC();   // peer may DSMEM-write our sdup after its first epilogue

    const float OMEGA = 1.8f, TWOSIG = 0.2f, INVC = 1.0f / 1.2f;

    float s_reg[2][8];
#pragma unroll
    for (int rr = 0; rr < 2; ++rr)
#pragma unroll
        for (int s = 0; s < 8; ++s) s_reg[rr][s] = 0.f;

    const float* Pw = g_P + (kq * 128) * DP + q * COLH + cs * 128 + lane * 4;
    const ull*   sK = sdup + (kq * 128) * SROW;
    float*     redw = redf + (cs * 4 + kq) * (RPC * 128) + lane * 4;

    for (int it = 0; it <= ITERS; ++it) {
        // ================= GEMM partial over K quarter =================
        ull acc[16][2];
#pragma unroll
        for (int r = 0; r < 16; ++r) { acc[r][0] = 0ull; acc[r][1] = 0ull; }

        ulonglong2 bufA[2], bufB[2];

#define LDP(buf, ii)                                                      \
        { const float* _p = Pw + (size_t)(ii) * DP;                       \
          buf[0] = *(const ulonglong2*)(_p);                              \
          buf[1] = *(const ulonglong2*)(_p + DP); }

#define COMPUTE(buf, ii)                                                  \
        { _Pragma("unroll")                                               \
          for (int u = 0; u < 2; ++u) {                                   \
            const ulonglong2* sc2 = (const ulonglong2*)(sK + ((ii)+u)*SROW); \
            ulonglong2 s0 = sc2[0], s1 = sc2[1], s2 = sc2[2], s3 = sc2[3]; \
            ulonglong2 s4 = sc2[4], s5 = sc2[5], s6 = sc2[6], s7 = sc2[7]; \
            ull p0 = buf[u].x, p1 = buf[u].y;                             \
            ffma2(acc[0][0],  s0.x, p0); ffma2(acc[0][1],  s0.x, p1);     \
            ffma2(acc[1][0],  s0.y, p0); ffma2(acc[1][1],  s0.y, p1);     \
            ffma2(acc[2][0],  s1.x, p0); ffma2(acc[2][1],  s1.x, p1);     \
            ffma2(acc[3][0],  s1.y, p0); ffma2(acc[3][1],  s1.y, p1);     \
            ffma2(acc[4][0],  s2.x, p0); ffma2(acc[4][1],  s2.x, p1);     \
            ffma2(acc[5][0],  s2.y, p0); ffma2(acc[5][1],  s2.y, p1);     \
            ffma2(acc[6][0],  s3.x, p0); ffma2(acc[6][1],  s3.x, p1);     \
            ffma2(acc[7][0],  s3.y, p0); ffma2(acc[7][1],  s3.y, p1);     \
            ffma2(acc[8][0],  s4.x, p0); ffma2(acc[8][1],  s4.x, p1);     \
            ffma2(acc[9][0],  s4.y, p0); ffma2(acc[9][1],  s4.y, p1);     \
            ffma2(acc[10][0], s5.x, p0); ffma2(acc[10][1], s5.x, p1);     \
            ffma2(acc[11][0], s5.y, p0); ffma2(acc[11][1], s5.y, p1);     \
            ffma2(acc[12][0], s6.x, p0); ffma2(acc[12][1], s6.x, p1);     \
            ffma2(acc[13][0], s6.y, p0); ffma2(acc[13][1], s6.y, p1);     \
            ffma2(acc[14][0], s7.x, p0); ffma2(acc[14][1], s7.x, p1);     \
            ffma2(acc[15][0], s7.y, p0); ffma2(acc[15][1], s7.y, p1);     \
          } }

        LDP(bufA, 0);
#pragma unroll 1
        for (int p = 0; p < 64; p += 2) {
            LDP(bufB, (p + 1) * 2);
            COMPUTE(bufA, p * 2);
            LDP(bufA, ((p + 2) * 2) & 127);   // last prefetch wraps harmlessly
            COMPUTE(bufB, (p + 1) * 2);
        }
#undef LDP
#undef COMPUTE

#pragma unroll
        for (int r = 0; r < 16; ++r) {
            float2 a = unpk(acc[r][0]), b = unpk(acc[r][1]);
            float4 v; v.x = a.x; v.y = a.y; v.z = b.x; v.w = b.y;
            *(float4*)(redw + r * 128) = v;
        }
        __syncthreads();

        // ================= epilogue: warp -> rows 2w, 2w+1 =================
        const int r0 = warp * 2;
        float z[2][8];
#pragma unroll
        for (int rr = 0; rr < 2; ++rr)
#pragma unroll
            for (int s = 0; s < 8; ++s) {
                int jl = s * 32 + lane;
                const float* rb = redf + (jl >> 7) * (4 * RPC * 128) + (r0 + rr) * 128 + (jl & 127);
                float g = rb[0] + rb[2048] + rb[4096] + rb[6144];
                z[rr][s] = g + qv[(r0 + rr) * COLH + jl];
            }

        if (it == ITERS) {
#pragma unroll
            for (int rr = 0; rr < 2; ++rr) {
                int gr = rowbase + r0 + rr;
#pragma unroll
                for (int s = 0; s < 8; ++s) {
                    int jg = q * COLH + s * 32 + lane;
                    if (jg < D) out[gr * D + jg] = z[rr][s];
                }
            }
            break;
        }

        float tp[2][8], part[2];
#pragma unroll
        for (int rr = 0; rr < 2; ++rr) {
            part[rr] = 0.f;
#pragma unroll
            for (int s = 0; s < 8; ++s) {
                int jl = s * 32 + lane;
                float t = (2.f * z[rr][s] - s_reg[rr][s] - TWOSIG * yv[(r0 + rr) * COLH + jl]) * INVC;
                tp[rr][s] = t;
                int jg = q * COLH + jl;
                if (jg >= NDIM && jg < D - 1) part[rr] += t * t;
            }
#pragma unroll
            for (int o = 16; o > 0; o >>= 1) part[rr] += __shfl_xor_sync(0xffffffffu, part[rr], o);
        }
        float tval[2];
#pragma unroll
        for (int rr = 0; rr < 2; ++rr)
            tval[rr] = q ? __shfl_sync(0xffffffffu, tp[rr][7], 19) : 0.f;  // j=499 -> jl=243=7*32+19

        if (lane < 2) {   // send {partial, tval} for row r0+lane to peer
            ull pv; asm("mov.b64 %0, {%1,%2};" : "=l"(pv) : "f"(part[lane]), "f"(tval[lane]));
            st_cluster_u64(peer_xbuf + (r0 + lane) * 8, pv);
        }
        CLUSTER_SYNC();   // #1: exchange visible

#pragma unroll
        for (int rr = 0; rr < 2; ++rr) {
            float2 pc = xbuf[r0 + rr];
            float nrm = sqrtf(part[rr] + pc.x);
            float tv  = q ? tval[rr] : pc.y;
            float f3 = 0.5f * (tv + nrm);
            float fu = f3 / (nrm + 1e-12f);
            bool case1 = (nrm <= tv);
            bool case2 = (!case1) && (nrm <= -tv);
#pragma unroll
            for (int s = 0; s < 8; ++s) {
                int jl = s * 32 + lane;
                int jg = q * COLH + jl;
                float t = tp[rr][s];
                float tk;
                if      (jg < NDIM)  tk = t;
                else if (jg < D - 1) tk = case1 ? t : (case2 ? 0.f : fu * t);
                else if (jg == D-1)  tk = case1 ? t : (case2 ? 0.f : f3);
                else                 tk = 0.f;
                float sn = s_reg[rr][s] + OMEGA * (tk - z[rr][s]);
                s_reg[rr][s] = sn;
                ull dv = dup2(sn);
                int sidx = jg * SROW + (r0 + rr);
                sdup[sidx] = dv;                                // local copy
                st_cluster_u64(peer_sdup + sidx * 8, dv);       // peer copy
            }
        }
        CLUSTER_SYNC();   // #2: peer s writes visible before next GEMM
    }
}

// ---------------- launch ----------------
extern "C" void kernel_launch(void* const* d_in, const int* in_sizes, int n_in,
                              void* d_out, int out_size) {
    const float* b    = (const float*)d_in[0];
    const float* c    = (const float*)d_in[1];
    const float* W1   = (const float*)d_in[2];
    const float* b1   = (const float*)d_in[3];
    const float* W2   = (const float*)d_in[4];
    const float* b2   = (const float*)d_in[5];
    const float* W3   = (const float*)d_in[6];
    const float* b3   = (const float*)d_in[7];
    const float* Aaug = (const float*)d_in[8];
    const float* Ainv = (const float*)d_in[9];
    float* out = (float*)d_out;

    void *p;
    cudaGetSymbolAddress(&p, g_h1); float* h1 = (float*)p;
    cudaGetSymbolAddress(&p, g_h2); float* h2 = (float*)p;
    cudaGetSymbolAddress(&p, g_y ); float* yy = (float*)p;
    cudaGetSymbolAddress(&p, g_q ); float* qq = (float*)p;

    computeP<<<(DP * DP) / 256, 256>>>(Aaug, Ainv);

    dim3 tb(16, 16);
    gemm16<<<dim3(HDIM / 16, BATCH / 16), tb>>>(b, c, W1, b1, h1, 500, HDIM, HDIM, FLAG_RELU | FLAG_CONCAT);
    gemm16<<<dim3(HDIM / 16, BATCH / 16), tb>>>(h1, nullptr, W2, b2, h2, HDIM, HDIM, HDIM, FLAG_RELU);
    gemm16<<<dim3(DP / 16, BATCH / 16), tb>>>(h2, nullptr, W3, b3, yy, HDIM, D, DP, 0);
    gemm16<<<dim3(DP / 16, BATCH / 16), tb>>>(b, nullptr, Ainv, nullptr, qq, MDIM, D, DP, FLAG_TRANSB);

    cudaFuncSetAttribute(iterate_kernel, cudaFuncAttributeMaxDynamicSharedMemorySize, SMEM_BYTES);
    iterate_kernel<<<(BATCH / RPC) * 2, 256, SMEM_BYTES>>>(out);
}